// round 2
// baseline (speedup 1.0000x reference)
#include <cuda_runtime.h>
#include <cuda_fp16.h>
#include <cstdint>

#define FEAT      2048
#define NPROBE    64
#define NGALLERY  256
#define NCLS      751
#define NPAD      768
#define BN_EPS    1e-5f

#define BM        128
#define BN        256
#define BK        64
#define KITERS    (FEAT / BK)     // 32
#define THREADS   512
#define WSCALE    64.0f
#define WSCALE_INV (1.0f / 64.0f)

// dynamic smem layout (byte offsets)
#define RAW0_OFF  0         // raw gallery f32 tile 128x64x4 = 32KB
#define RAW1_OFF  32768
#define A0_OFF    65536     // A fp16 tile 128x64x2 = 16KB
#define A1_OFF    81920
#define B0_OFF    98304     // B fp16 tile 256x64x2 = 32KB
#define B1_OFF    131072
#define SMEM_TOTAL 163840   // 160 KB

// ---------------- device scratch ----------------
__device__ __align__(16) float g_scale[FEAT];
__device__ __align__(16) float g_mean[FEAT];
__device__ __align__(16) float g_cconst[NPAD];
__device__ __align__(16) __half g_W16[NPAD * FEAT];

// ---------------- helpers ----------------
__device__ __forceinline__ uint32_t smem_u32(const void* p) {
    uint32_t a;
    asm("{ .reg .u64 t; cvta.to.shared.u64 t, %1; cvt.u32.u64 %0, t; }"
        : "=r"(a) : "l"(p));
    return a;
}

__device__ __forceinline__ uint32_t sw128(uint32_t off) {
    return off ^ ((off >> 3) & 0x70);
}

__device__ __forceinline__ void cp16(uint32_t dst, const void* src) {
    asm volatile("cp.async.cg.shared.global [%0], [%1], 16;"
                 :: "r"(dst), "l"(src) : "memory");
}
#define CP_COMMIT() asm volatile("cp.async.commit_group;" ::: "memory")
#define CP_WAIT0()  asm volatile("cp.async.wait_group 0;" ::: "memory")

__device__ __forceinline__ void ldsm4(uint32_t& r0, uint32_t& r1,
                                      uint32_t& r2, uint32_t& r3, uint32_t addr) {
    asm volatile("ldmatrix.sync.aligned.m8n8.x4.shared.b16 {%0,%1,%2,%3}, [%4];"
                 : "=r"(r0), "=r"(r1), "=r"(r2), "=r"(r3) : "r"(addr));
}

__device__ __forceinline__ void mma16816(float* c, const uint32_t* a,
                                         const uint32_t* b) {
    asm volatile(
        "mma.sync.aligned.m16n8k16.row.col.f32.f16.f16.f32 "
        "{%0,%1,%2,%3}, {%4,%5,%6,%7}, {%8,%9}, {%0,%1,%2,%3};"
        : "+f"(c[0]), "+f"(c[1]), "+f"(c[2]), "+f"(c[3])
        : "r"(a[0]), "r"(a[1]), "r"(a[2]), "r"(a[3]), "r"(b[0]), "r"(b[1]));
}

// ---------------- kernel 1: closed-form BN statistics ----------------
__global__ void stats_kernel(const float* __restrict__ probe,
                             const float* __restrict__ gallery,
                             const float* __restrict__ gamma) {
    int f = blockIdx.x * blockDim.x + threadIdx.x;
    if (f >= FEAT) return;
    float sp1 = 0.f, sp2 = 0.f, sp3 = 0.f, sp4 = 0.f;
    for (int i = 0; i < NPROBE; i++) {
        float v = probe[i * FEAT + f];
        float v2 = v * v;
        sp1 += v; sp2 += v2; sp3 += v2 * v; sp4 += v2 * v2;
    }
    float sg1 = 0.f, sg2 = 0.f, sg3 = 0.f, sg4 = 0.f;
    for (int j = 0; j < NGALLERY; j++) {
        float v = gallery[j * FEAT + f];
        float v2 = v * v;
        sg1 += v; sg2 += v2; sg3 += v2 * v; sg4 += v2 * v2;
    }
    const float ip = 1.f / NPROBE, ig = 1.f / NGALLERY;
    float mp1 = sp1 * ip, mp2 = sp2 * ip, mp3 = sp3 * ip, mp4 = sp4 * ip;
    float mg1 = sg1 * ig, mg2 = sg2 * ig, mg3 = sg3 * ig, mg4 = sg4 * ig;
    // exact identities: batch is the full (i,j) cartesian product
    float mean = mp2 + mg2 - 2.f * mp1 * mg1;
    float ed2  = mp4 - 4.f * mp3 * mg1 + 6.f * mp2 * mg2 - 4.f * mp1 * mg3 + mg4;
    float var  = ed2 - mean * mean;
    g_mean[f]  = mean;
    g_scale[f] = gamma[f] * rsqrtf(var + BN_EPS);
}

// ---------------- kernel 2: fp16 W' = w*scale*64, cconst ----------------
__global__ void prep_kernel(const float* __restrict__ W,
                            const float* __restrict__ beta,
                            const float* __restrict__ bias) {
    int c = blockIdx.x;        // 0..767
    int tid = threadIdx.x;     // 256
    float acc = 0.f;
    for (int f = tid; f < FEAT; f += 256) {
        float w = (c < NCLS) ? W[c * FEAT + f] : 0.f;
        g_W16[(size_t)c * FEAT + f] = __float2half_rn(w * g_scale[f] * WSCALE);
        acc += w * beta[f];
    }
    __shared__ float red[256];
    red[tid] = acc;
    __syncthreads();
    for (int s = 128; s > 0; s >>= 1) {
        if (tid < s) red[tid] += red[tid + s];
        __syncthreads();
    }
    if (tid == 0) g_cconst[c] = red[0] + ((c < NCLS) ? bias[c] : 0.f);
}

// ---------------- kernel 3: fused (p-g)^2-mean fp16 HMMA GEMM ----------------
// C[16384,768] = A[16384,2048] * W'^T, A built on the fly.
// CTA tile 128x256, BK=64, 512 threads (16 warps: 2 along M x 8 along N).
__global__ void __launch_bounds__(THREADS, 1)
gemm_kernel(const float* __restrict__ probe,
            const float* __restrict__ gallery,
            float* __restrict__ out) {
    extern __shared__ char smem[];
    const uint32_t sb = smem_u32(smem);
    const int tid = threadIdx.x;
    const int lid = tid & 31;
    const int wid = tid >> 5;

    const int ct = blockIdx.x;            // 0..2
    const int rt = blockIdx.y;            // 0..127
    const int n0 = rt * BM;
    const int i_probe = rt >> 1;
    const int j0 = (rt & 1) * BM;
    const int c0 = ct * BN;
    const float* prow = probe + (size_t)i_probe * FEAT;

    // producer thread mapping
    const int ar = tid >> 4;              // A row base (0..31), +32 per pass
    const int au = tid & 15;              // 16B chunk within 256B raw row
    const int br = tid >> 3;              // B row base (0..63), +64 per pass
    const int bu = tid & 7;               // 16B chunk within 128B B row

    // consumer (MMA) mapping
    const int wm = wid & 1;               // 2 warps along M
    const int wn = wid >> 1;              // 8 warps along N
    const int mbase = wm * 64;
    const int nbase = wn * 32;
    const int a_row  = ((lid >> 3) & 1) * 8 + (lid & 7);
    const int a_colb = (lid >> 4) * 16;
    const int b_row  = (lid >> 4) * 8 + (lid & 7);
    const int b_colb = ((lid >> 3) & 1) * 16;

    float acc[4][4][4];
    #pragma unroll
    for (int im = 0; im < 4; im++)
        #pragma unroll
        for (int in = 0; in < 4; in++)
            #pragma unroll
            for (int r = 0; r < 4; r++) acc[im][in][r] = 0.f;

    // ---- producer helpers ----
    auto issue_raw = [&](int kt, uint32_t buf) {
        const int k0 = kt * BK;
        #pragma unroll
        for (int c = 0; c < 4; c++) {
            int row = ar + c * 32;
            cp16(sb + buf + row * 256 + au * 16,
                 &gallery[(size_t)(j0 + row) * FEAT + k0 + au * 4]);
        }
    };
    auto issue_B = [&](int kt, uint32_t buf) {
        const int k0 = kt * BK;
        #pragma unroll
        for (int c = 0; c < 4; c++) {
            int row = br + c * 64;
            cp16(sb + buf + sw128(row * 128 + bu * 16),
                 &g_W16[(size_t)(c0 + row) * FEAT + k0 + bu * 8]);
        }
    };
    auto convert = [&](int kt, uint32_t rawbuf, uint32_t abuf) {
        const int k0 = kt * BK;
        const float4 pv = __ldg((const float4*)&prow[k0 + au * 4]);
        const float4 mv = *(const float4*)&g_mean[k0 + au * 4];
        #pragma unroll
        for (int c = 0; c < 4; c++) {
            int row = ar + c * 32;
            float4 gv = *(const float4*)(smem + rawbuf + row * 256 + au * 16);
            float d0 = pv.x - gv.x; d0 = d0 * d0 - mv.x;
            float d1 = pv.y - gv.y; d1 = d1 * d1 - mv.y;
            float d2 = pv.z - gv.z; d2 = d2 * d2 - mv.z;
            float d3 = pv.w - gv.w; d3 = d3 * d3 - mv.w;
            __half2 h01 = __floats2half2_rn(d0, d1);
            __half2 h23 = __floats2half2_rn(d2, d3);
            uint2 val;
            val.x = *reinterpret_cast<uint32_t*>(&h01);
            val.y = *reinterpret_cast<uint32_t*>(&h23);
            *(uint2*)(smem + abuf + sw128(row * 128 + au * 8)) = val;
        }
    };
    auto mma_stage = [&](uint32_t abuf, uint32_t bbuf) {
        #pragma unroll
        for (int ik = 0; ik < 4; ik++) {
            uint32_t a[4][4];
            #pragma unroll
            for (int im = 0; im < 4; im++) {
                uint32_t addr = sb + abuf +
                    sw128((mbase + im * 16 + a_row) * 128 + ik * 32 + a_colb);
                ldsm4(a[im][0], a[im][1], a[im][2], a[im][3], addr);
            }
            uint32_t b[8];
            #pragma unroll
            for (int nb = 0; nb < 2; nb++) {
                uint32_t addr = sb + bbuf +
                    sw128((nbase + nb * 16 + b_row) * 128 + ik * 32 + b_colb);
                ldsm4(b[nb * 4 + 0], b[nb * 4 + 1], b[nb * 4 + 2], b[nb * 4 + 3], addr);
            }
            #pragma unroll
            for (int im = 0; im < 4; im++)
                #pragma unroll
                for (int in = 0; in < 4; in++)
                    mma16816(acc[im][in], a[im], &b[in * 2]);
        }
    };

    // ---- prologue: stages 0 and 1 in flight, convert stage 0 ----
    issue_raw(0, RAW0_OFF); issue_B(0, B0_OFF);
    issue_raw(1, RAW1_OFF); issue_B(1, B1_OFF);
    CP_COMMIT();
    CP_WAIT0();                 // own chunks visible to this thread
    convert(0, RAW0_OFF, A0_OFF);
    __syncthreads();            // A0/B0 visible to all

    // ---- main loop ----
    for (int kt = 0; kt < KITERS; kt++) {
        const int cur = kt & 1;
        if (kt + 2 < KITERS) issue_raw(kt + 2, cur ? RAW1_OFF : RAW0_OFF);
        if (kt + 1 < KITERS) issue_B(kt + 1, cur ? B0_OFF : B1_OFF);
        CP_COMMIT();
        mma_stage(cur ? A1_OFF : A0_OFF, cur ? B1_OFF : B0_OFF);
        CP_WAIT0();
        if (kt + 1 < KITERS)
            convert(kt + 1, cur ? RAW0_OFF : RAW1_OFF, cur ? A0_OFF : A1_OFF);
        __syncthreads();
    }

    // ---- epilogue: acc/64 + cconst, direct fp32 stores ----
    #pragma unroll
    for (int im = 0; im < 4; im++) {
        const int row = n0 + mbase + im * 16 + (lid >> 2);
        #pragma unroll
        for (int in = 0; in < 4; in++) {
            const int col = c0 + nbase + in * 8 + (lid & 3) * 2;
            const float cc0 = __ldg(&g_cconst[col]);
            const float cc1 = __ldg(&g_cconst[col + 1 < NPAD ? col + 1 : col]);
            if (col < NCLS)
                out[(size_t)row * NCLS + col] = acc[im][in][0] * WSCALE_INV + cc0;
            if (col + 1 < NCLS)
                out[(size_t)row * NCLS + col + 1] = acc[im][in][1] * WSCALE_INV + cc1;
            if (col < NCLS)
                out[(size_t)(row + 8) * NCLS + col] = acc[im][in][2] * WSCALE_INV + cc0;
            if (col + 1 < NCLS)
                out[(size_t)(row + 8) * NCLS + col + 1] = acc[im][in][3] * WSCALE_INV + cc1;
        }
    }
}

// ---------------- launch ----------------
extern "C" void kernel_launch(void* const* d_in, const int* in_sizes, int n_in,
                              void* d_out, int out_size) {
    const float* probe   = (const float*)d_in[0];
    const float* gallery = (const float*)d_in[1];
    const float* gamma   = (const float*)d_in[2];
    const float* beta    = (const float*)d_in[3];
    const float* W       = (const float*)d_in[4];
    const float* bias    = (const float*)d_in[5];
    float* out = (float*)d_out;

    stats_kernel<<<FEAT / 256, 256>>>(probe, gallery, gamma);
    prep_kernel<<<NPAD, 256>>>(W, beta, bias);

    static bool attr_set = false;
    if (!attr_set) {
        cudaFuncSetAttribute(gemm_kernel,
                             cudaFuncAttributeMaxDynamicSharedMemorySize, SMEM_TOTAL);
        attr_set = true;
    }
    gemm_kernel<<<dim3(3, 128, 1), THREADS, SMEM_TOTAL>>>(probe, gallery, out);
}

// round 3
// speedup vs baseline: 1.1300x; 1.1300x over previous
#include <cuda_runtime.h>
#include <cuda_fp16.h>
#include <cstdint>

#define FEAT      2048
#define NPROBE    64
#define NGALLERY  256
#define NROWS     16384           // NPROBE * NGALLERY
#define NCLS      751
#define NPAD      768
#define BN_EPS    1e-5f

#define BM        128
#define BN        256
#define BK        64
#define KITERS    (FEAT / BK)     // 32
#define THREADS   256             // 8 warps, warp tile 64x64
#define WSCALE    64.0f
#define WSCALE_INV (1.0f / 64.0f)

// 4-stage smem pipeline: per stage A 16KB + B 32KB = 48KB
#define STAGE_BYTES 49152
#define NSTAGES     4
#define SMEM_TOTAL  (NSTAGES * STAGE_BYTES)   // 192 KB

#define NPART 10   // 2 probe splits + 8 gallery splits (32 rows each)

// ---------------- device scratch ----------------
__device__ __align__(16) float g_part[NPART * 4 * FEAT];
__device__ __align__(16) float g_scale[FEAT];
__device__ __align__(16) float g_mean[FEAT];
__device__ __align__(16) float g_cconst[NPAD];
__device__ __align__(16) __half g_W16[NPAD * FEAT];     // 3 MB
__device__ __align__(16) __half g_A16[(size_t)NROWS * FEAT]; // 64 MB

// ---------------- helpers ----------------
__device__ __forceinline__ uint32_t smem_u32(const void* p) {
    uint32_t a;
    asm("{ .reg .u64 t; cvta.to.shared.u64 t, %1; cvt.u32.u64 %0, t; }"
        : "=r"(a) : "l"(p));
    return a;
}
__device__ __forceinline__ uint32_t sw128(uint32_t off) {
    return off ^ ((off >> 3) & 0x70);
}
__device__ __forceinline__ void cp16(uint32_t dst, const void* src) {
    asm volatile("cp.async.cg.shared.global [%0], [%1], 16;"
                 :: "r"(dst), "l"(src) : "memory");
}
#define CP_COMMIT() asm volatile("cp.async.commit_group;" ::: "memory")
#define CP_WAIT2()  asm volatile("cp.async.wait_group 2;" ::: "memory")

__device__ __forceinline__ void ldsm4(uint32_t* r, uint32_t addr) {
    asm volatile("ldmatrix.sync.aligned.m8n8.x4.shared.b16 {%0,%1,%2,%3}, [%4];"
                 : "=r"(r[0]), "=r"(r[1]), "=r"(r[2]), "=r"(r[3]) : "r"(addr));
}
__device__ __forceinline__ void mma16816(float* c, const uint32_t* a,
                                         const uint32_t* b) {
    asm volatile(
        "mma.sync.aligned.m16n8k16.row.col.f32.f16.f16.f32 "
        "{%0,%1,%2,%3}, {%4,%5,%6,%7}, {%8,%9}, {%0,%1,%2,%3};"
        : "+f"(c[0]), "+f"(c[1]), "+f"(c[2]), "+f"(c[3])
        : "r"(a[0]), "r"(a[1]), "r"(a[2]), "r"(a[3]), "r"(b[0]), "r"(b[1]));
}

// ---------------- kernel 1a: partial moments (80 blocks) ----------------
__global__ void stats_part_kernel(const float* __restrict__ probe,
                                  const float* __restrict__ gallery) {
    const int f = blockIdx.x * 256 + threadIdx.x;   // grid.x = 8
    const int y = blockIdx.y;                        // 0..9
    const float* src = (y < 2) ? probe : gallery;
    const int r0 = (y < 2) ? y * 32 : (y - 2) * 32;
    float s1 = 0.f, s2 = 0.f, s3 = 0.f, s4 = 0.f;
    #pragma unroll 8
    for (int r = 0; r < 32; r++) {
        float v = src[(size_t)(r0 + r) * FEAT + f];
        float v2 = v * v;
        s1 += v; s2 += v2; s3 += v2 * v; s4 += v2 * v2;
    }
    g_part[(y * 4 + 0) * FEAT + f] = s1;
    g_part[(y * 4 + 1) * FEAT + f] = s2;
    g_part[(y * 4 + 2) * FEAT + f] = s3;
    g_part[(y * 4 + 3) * FEAT + f] = s4;
}

// ---------------- kernel 1b: finalize BN stats ----------------
__global__ void stats_final_kernel(const float* __restrict__ gamma) {
    const int f = blockIdx.x * 256 + threadIdx.x;
    float sp1 = 0.f, sp2 = 0.f, sp3 = 0.f, sp4 = 0.f;
    float sg1 = 0.f, sg2 = 0.f, sg3 = 0.f, sg4 = 0.f;
    #pragma unroll
    for (int y = 0; y < 2; y++) {
        sp1 += g_part[(y * 4 + 0) * FEAT + f];
        sp2 += g_part[(y * 4 + 1) * FEAT + f];
        sp3 += g_part[(y * 4 + 2) * FEAT + f];
        sp4 += g_part[(y * 4 + 3) * FEAT + f];
    }
    #pragma unroll
    for (int y = 2; y < 10; y++) {
        sg1 += g_part[(y * 4 + 0) * FEAT + f];
        sg2 += g_part[(y * 4 + 1) * FEAT + f];
        sg3 += g_part[(y * 4 + 2) * FEAT + f];
        sg4 += g_part[(y * 4 + 3) * FEAT + f];
    }
    const float ip = 1.f / NPROBE, ig = 1.f / NGALLERY;
    float mp1 = sp1 * ip, mp2 = sp2 * ip, mp3 = sp3 * ip, mp4 = sp4 * ip;
    float mg1 = sg1 * ig, mg2 = sg2 * ig, mg3 = sg3 * ig, mg4 = sg4 * ig;
    // exact identities: batch = full (i,j) cartesian product of (p_i-g_j)^2
    float mean = mp2 + mg2 - 2.f * mp1 * mg1;
    float ed2  = mp4 - 4.f * mp3 * mg1 + 6.f * mp2 * mg2 - 4.f * mp1 * mg3 + mg4;
    float var  = ed2 - mean * mean;
    g_mean[f]  = mean;
    g_scale[f] = gamma[f] * rsqrtf(var + BN_EPS);
}

// ---------------- kernel 2: fp16 W' = w*scale*WSCALE, cconst ----------------
__global__ void prep_kernel(const float* __restrict__ W,
                            const float* __restrict__ beta,
                            const float* __restrict__ bias) {
    const int c = blockIdx.x;        // 0..767
    const int tid = threadIdx.x;     // 256
    const int f0 = tid * 8;
    float acc = 0.f;
    float w[8];
    if (c < NCLS) {
        float4 w0 = *(const float4*)&W[(size_t)c * FEAT + f0];
        float4 w1 = *(const float4*)&W[(size_t)c * FEAT + f0 + 4];
        w[0] = w0.x; w[1] = w0.y; w[2] = w0.z; w[3] = w0.w;
        w[4] = w1.x; w[5] = w1.y; w[6] = w1.z; w[7] = w1.w;
    } else {
        #pragma unroll
        for (int k = 0; k < 8; k++) w[k] = 0.f;
    }
    __half h[8];
    #pragma unroll
    for (int k = 0; k < 8; k++) {
        float s = g_scale[f0 + k];
        h[k] = __float2half_rn(w[k] * s * WSCALE);
        acc += w[k] * beta[f0 + k];
    }
    *(uint4*)&g_W16[(size_t)c * FEAT + f0] = *(uint4*)h;
    // block reduce
    #pragma unroll
    for (int o = 16; o > 0; o >>= 1)
        acc += __shfl_down_sync(0xFFFFFFFFu, acc, o);
    __shared__ float red[8];
    if ((tid & 31) == 0) red[tid >> 5] = acc;
    __syncthreads();
    if (tid == 0) {
        float t = 0.f;
        #pragma unroll
        for (int k = 0; k < 8; k++) t += red[k];
        g_cconst[c] = t + ((c < NCLS) ? bias[c] : 0.f);
    }
}

// ---------------- kernel 3: A16[n][f] = fp16((p-g)^2 - mean) ----------------
// grid (64, 16): block = (probe i, chunk of 16 gallery rows). 256 threads.
__global__ void a16_kernel(const float* __restrict__ probe,
                           const float* __restrict__ gallery) {
    const int i = blockIdx.x;
    const int jc = blockIdx.y;
    const int f0 = threadIdx.x * 8;
    float4 p0 = *(const float4*)&probe[(size_t)i * FEAT + f0];
    float4 p1 = *(const float4*)&probe[(size_t)i * FEAT + f0 + 4];
    float4 m0 = *(const float4*)&g_mean[f0];
    float4 m1 = *(const float4*)&g_mean[f0 + 4];
    #pragma unroll 4
    for (int jj = 0; jj < 16; jj++) {
        const int j = jc * 16 + jj;
        float4 gv0 = *(const float4*)&gallery[(size_t)j * FEAT + f0];
        float4 gv1 = *(const float4*)&gallery[(size_t)j * FEAT + f0 + 4];
        float d[8];
        d[0] = p0.x - gv0.x; d[0] = d[0] * d[0] - m0.x;
        d[1] = p0.y - gv0.y; d[1] = d[1] * d[1] - m0.y;
        d[2] = p0.z - gv0.z; d[2] = d[2] * d[2] - m0.z;
        d[3] = p0.w - gv0.w; d[3] = d[3] * d[3] - m0.w;
        d[4] = p1.x - gv1.x; d[4] = d[4] * d[4] - m1.x;
        d[5] = p1.y - gv1.y; d[5] = d[5] * d[5] - m1.y;
        d[6] = p1.z - gv1.z; d[6] = d[6] * d[6] - m1.z;
        d[7] = p1.w - gv1.w; d[7] = d[7] * d[7] - m1.w;
        __half h[8];
        #pragma unroll
        for (int k = 0; k < 8; k++) h[k] = __float2half_rn(d[k]);
        *(uint4*)&g_A16[(size_t)(i * NGALLERY + j) * FEAT + f0] = *(uint4*)h;
    }
}

// ---------------- kernel 4: fp16 HMMA GEMM, 4-stage cp.async pipeline ------
// C[16384,768] = A16 * W16^T. Tile 128x256x64, 8 warps, warp tile 64x64.
__global__ void __launch_bounds__(THREADS, 1)
gemm_kernel(float* __restrict__ out) {
    extern __shared__ char smem[];
    const uint32_t sb = smem_u32(smem);
    const int tid = threadIdx.x;
    const int lid = tid & 31;
    const int wid = tid >> 5;

    const int ct = blockIdx.x;            // 0..2
    const int rt = blockIdx.y;            // 0..127
    const int n0 = rt * BM;
    const int c0 = ct * BN;

    // producer mapping: 16B chunks, 8 per 128B row
    const int pr = tid >> 3;              // row base 0..31
    const int pu = tid & 7;               // chunk in row

    // consumer mapping: warp grid 2 (M) x 4 (N), warp tile 64x64
    const int wm = wid >> 2;              // 0..1
    const int wn = wid & 3;               // 0..3
    const int mbase = wm * 64;
    const int nbase = wn * 64;
    const int a_row  = ((lid >> 3) & 1) * 8 + (lid & 7);
    const int a_colb = (lid >> 4) * 16;
    const int b_row  = (lid >> 4) * 8 + (lid & 7);
    const int b_colb = ((lid >> 3) & 1) * 16;

    float acc[4][8][4];
    #pragma unroll
    for (int im = 0; im < 4; im++)
        #pragma unroll
        for (int in = 0; in < 8; in++)
            #pragma unroll
            for (int r = 0; r < 4; r++) acc[im][in][r] = 0.f;

    auto issue = [&](int kt) {
        const uint32_t st = (uint32_t)(kt & (NSTAGES - 1)) * STAGE_BYTES;
        const int k0 = kt * BK;
        // A tile: 128 rows x 128 B
        #pragma unroll
        for (int c = 0; c < 4; c++) {
            int row = pr + c * 32;
            cp16(sb + st + sw128(row * 128 + pu * 16),
                 &g_A16[(size_t)(n0 + row) * FEAT + k0 + pu * 8]);
        }
        // B tile: 256 rows x 128 B
        #pragma unroll
        for (int c = 0; c < 8; c++) {
            int row = pr + c * 32;
            cp16(sb + st + 16384 + sw128(row * 128 + pu * 16),
                 &g_W16[(size_t)(c0 + row) * FEAT + k0 + pu * 8]);
        }
    };

    // prologue: 3 stages in flight
    issue(0); CP_COMMIT();
    issue(1); CP_COMMIT();
    issue(2); CP_COMMIT();

    for (int kt = 0; kt < KITERS; kt++) {
        CP_WAIT2();            // stage kt complete (2 newer groups may pend)
        __syncthreads();       // visibility + buffer (kt-1)%4 free for reuse
        if (kt + 3 < KITERS) issue(kt + 3);
        CP_COMMIT();           // empty group near tail keeps count invariant

        const uint32_t abuf = (uint32_t)(kt & (NSTAGES - 1)) * STAGE_BYTES;
        const uint32_t bbuf = abuf + 16384;
        #pragma unroll
        for (int ik = 0; ik < 4; ik++) {
            uint32_t a[4][4];
            #pragma unroll
            for (int im = 0; im < 4; im++)
                ldsm4(a[im], sb + abuf +
                      sw128((mbase + im * 16 + a_row) * 128 + ik * 32 + a_colb));
            uint32_t b[16];
            #pragma unroll
            for (int nb = 0; nb < 4; nb++)
                ldsm4(&b[nb * 4], sb + bbuf +
                      sw128((nbase + nb * 16 + b_row) * 128 + ik * 32 + b_colb));
            #pragma unroll
            for (int im = 0; im < 4; im++)
                #pragma unroll
                for (int in = 0; in < 8; in++)
                    mma16816(acc[im][in], a[im], &b[in * 2]);
        }
    }

    // epilogue: acc/WSCALE + cconst
    #pragma unroll
    for (int im = 0; im < 4; im++) {
        const int row = n0 + mbase + im * 16 + (lid >> 2);
        #pragma unroll
        for (int in = 0; in < 8; in++) {
            const int col = c0 + nbase + in * 8 + (lid & 3) * 2;
            const float cc0 = g_cconst[col];
            const float cc1 = g_cconst[col + 1 < NPAD ? col + 1 : col];
            if (col < NCLS)
                out[(size_t)row * NCLS + col] = acc[im][in][0] * WSCALE_INV + cc0;
            if (col + 1 < NCLS)
                out[(size_t)row * NCLS + col + 1] = acc[im][in][1] * WSCALE_INV + cc1;
            if (col < NCLS)
                out[(size_t)(row + 8) * NCLS + col] = acc[im][in][2] * WSCALE_INV + cc0;
            if (col + 1 < NCLS)
                out[(size_t)(row + 8) * NCLS + col + 1] = acc[im][in][3] * WSCALE_INV + cc1;
        }
    }
}

// ---------------- launch ----------------
extern "C" void kernel_launch(void* const* d_in, const int* in_sizes, int n_in,
                              void* d_out, int out_size) {
    const float* probe   = (const float*)d_in[0];
    const float* gallery = (const float*)d_in[1];
    const float* gamma   = (const float*)d_in[2];
    const float* beta    = (const float*)d_in[3];
    const float* W       = (const float*)d_in[4];
    const float* bias    = (const float*)d_in[5];
    float* out = (float*)d_out;

    stats_part_kernel<<<dim3(8, 10), 256>>>(probe, gallery);
    stats_final_kernel<<<8, 256>>>(gamma);
    a16_kernel<<<dim3(64, 16), 256>>>(probe, gallery);
    prep_kernel<<<NPAD, 256>>>(W, beta, bias);

    static bool attr_set = false;
    if (!attr_set) {
        cudaFuncSetAttribute(gemm_kernel,
                             cudaFuncAttributeMaxDynamicSharedMemorySize, SMEM_TOTAL);
        attr_set = true;
    }
    gemm_kernel<<<dim3(3, 128, 1), THREADS, SMEM_TOTAL>>>(out);
}

// round 4
// speedup vs baseline: 1.1342x; 1.0037x over previous
#include <cuda_runtime.h>
#include <cuda_fp16.h>
#include <cstdint>

#define FEAT      2048
#define NPROBE    64
#define NGALLERY  256
#define NROWS     16384           // NPROBE * NGALLERY
#define NCLS      751
#define NPAD      768
#define BN_EPS    1e-5f

#define BM        128
#define BN        256
#define BK        64
#define KITERS    (FEAT / BK)     // 32
#define THREADS   256             // 8 warps, warp tile 64x64
#define WSCALE    64.0f
#define WSCALE_INV (1.0f / 64.0f)

// 4-stage smem pipeline: per stage A 16KB + B 32KB = 48KB
#define STAGE_BYTES 49152
#define NSTAGES     4
#define SMEM_TOTAL  (NSTAGES * STAGE_BYTES)   // 192 KB

#define NPART 10

// ---------------- device scratch ----------------
__device__ __align__(16) float g_part[NPART * 4 * FEAT];
__device__ __align__(16) float g_scale[FEAT];
__device__ __align__(16) float g_mean[FEAT];
__device__ __align__(16) float g_cconst[NPAD];
__device__ __align__(16) __half g_W16[NPAD * FEAT];          // 3 MB
__device__ __align__(16) __half g_A16[(size_t)NROWS * FEAT]; // 64 MB

// ---------------- helpers ----------------
__device__ __forceinline__ uint32_t smem_u32(const void* p) {
    uint32_t a;
    asm("{ .reg .u64 t; cvta.to.shared.u64 t, %1; cvt.u32.u64 %0, t; }"
        : "=r"(a) : "l"(p));
    return a;
}
__device__ __forceinline__ uint32_t sw128(uint32_t off) {
    return off ^ ((off >> 3) & 0x70);
}
__device__ __forceinline__ void cp16(uint32_t dst, const void* src) {
    asm volatile("cp.async.cg.shared.global [%0], [%1], 16;"
                 :: "r"(dst), "l"(src) : "memory");
}
#define CP_COMMIT() asm volatile("cp.async.commit_group;" ::: "memory")
#define CP_WAIT2()  asm volatile("cp.async.wait_group 2;" ::: "memory")

__device__ __forceinline__ void ldsm4(uint32_t* r, uint32_t addr) {
    asm volatile("ldmatrix.sync.aligned.m8n8.x4.shared.b16 {%0,%1,%2,%3}, [%4];"
                 : "=r"(r[0]), "=r"(r[1]), "=r"(r[2]), "=r"(r[3]) : "r"(addr));
}
__device__ __forceinline__ void mma16816(float* c, const uint32_t* a,
                                         const uint32_t* b) {
    asm volatile(
        "mma.sync.aligned.m16n8k16.row.col.f32.f16.f16.f32 "
        "{%0,%1,%2,%3}, {%4,%5,%6,%7}, {%8,%9}, {%0,%1,%2,%3};"
        : "+f"(c[0]), "+f"(c[1]), "+f"(c[2]), "+f"(c[3])
        : "r"(a[0]), "r"(a[1]), "r"(a[2]), "r"(a[3]), "r"(b[0]), "r"(b[1]));
}

// ---------------- kernel 1a: partial moments (80 blocks) ----------------
__global__ void stats_part_kernel(const float* __restrict__ probe,
                                  const float* __restrict__ gallery) {
    const int f = blockIdx.x * 256 + threadIdx.x;
    const int y = blockIdx.y;
    const float* src = (y < 2) ? probe : gallery;
    const int r0 = (y < 2) ? y * 32 : (y - 2) * 32;
    float s1 = 0.f, s2 = 0.f, s3 = 0.f, s4 = 0.f;
    #pragma unroll 8
    for (int r = 0; r < 32; r++) {
        float v = src[(size_t)(r0 + r) * FEAT + f];
        float v2 = v * v;
        s1 += v; s2 += v2; s3 += v2 * v; s4 += v2 * v2;
    }
    g_part[(y * 4 + 0) * FEAT + f] = s1;
    g_part[(y * 4 + 1) * FEAT + f] = s2;
    g_part[(y * 4 + 2) * FEAT + f] = s3;
    g_part[(y * 4 + 3) * FEAT + f] = s4;
}

// ---------------- kernel 1b: finalize BN stats ----------------
__global__ void stats_final_kernel(const float* __restrict__ gamma) {
    const int f = blockIdx.x * 256 + threadIdx.x;
    float sp1 = 0.f, sp2 = 0.f, sp3 = 0.f, sp4 = 0.f;
    float sg1 = 0.f, sg2 = 0.f, sg3 = 0.f, sg4 = 0.f;
    #pragma unroll
    for (int y = 0; y < 2; y++) {
        sp1 += g_part[(y * 4 + 0) * FEAT + f];
        sp2 += g_part[(y * 4 + 1) * FEAT + f];
        sp3 += g_part[(y * 4 + 2) * FEAT + f];
        sp4 += g_part[(y * 4 + 3) * FEAT + f];
    }
    #pragma unroll
    for (int y = 2; y < 10; y++) {
        sg1 += g_part[(y * 4 + 0) * FEAT + f];
        sg2 += g_part[(y * 4 + 1) * FEAT + f];
        sg3 += g_part[(y * 4 + 2) * FEAT + f];
        sg4 += g_part[(y * 4 + 3) * FEAT + f];
    }
    const float ip = 1.f / NPROBE, ig = 1.f / NGALLERY;
    float mp1 = sp1 * ip, mp2 = sp2 * ip, mp3 = sp3 * ip, mp4 = sp4 * ip;
    float mg1 = sg1 * ig, mg2 = sg2 * ig, mg3 = sg3 * ig, mg4 = sg4 * ig;
    float mean = mp2 + mg2 - 2.f * mp1 * mg1;
    float ed2  = mp4 - 4.f * mp3 * mg1 + 6.f * mp2 * mg2 - 4.f * mp1 * mg3 + mg4;
    float var  = ed2 - mean * mean;
    g_mean[f]  = mean;
    g_scale[f] = gamma[f] * rsqrtf(var + BN_EPS);
}

// ---------------- kernel 2: fp16 W' = w*scale*WSCALE, cconst ----------------
__global__ void prep_kernel(const float* __restrict__ W,
                            const float* __restrict__ beta,
                            const float* __restrict__ bias) {
    const int c = blockIdx.x;
    const int tid = threadIdx.x;
    const int f0 = tid * 8;
    float acc = 0.f;
    float w[8];
    if (c < NCLS) {
        float4 w0 = *(const float4*)&W[(size_t)c * FEAT + f0];
        float4 w1 = *(const float4*)&W[(size_t)c * FEAT + f0 + 4];
        w[0] = w0.x; w[1] = w0.y; w[2] = w0.z; w[3] = w0.w;
        w[4] = w1.x; w[5] = w1.y; w[6] = w1.z; w[7] = w1.w;
    } else {
        #pragma unroll
        for (int k = 0; k < 8; k++) w[k] = 0.f;
    }
    __half h[8];
    #pragma unroll
    for (int k = 0; k < 8; k++) {
        float s = g_scale[f0 + k];
        h[k] = __float2half_rn(w[k] * s * WSCALE);
        acc += w[k] * beta[f0 + k];
    }
    *(uint4*)&g_W16[(size_t)c * FEAT + f0] = *(uint4*)h;
    #pragma unroll
    for (int o = 16; o > 0; o >>= 1)
        acc += __shfl_down_sync(0xFFFFFFFFu, acc, o);
    __shared__ float red[8];
    if ((tid & 31) == 0) red[tid >> 5] = acc;
    __syncthreads();
    if (tid == 0) {
        float t = 0.f;
        #pragma unroll
        for (int k = 0; k < 8; k++) t += red[k];
        g_cconst[c] = t + ((c < NCLS) ? bias[c] : 0.f);
    }
}

// ---------------- kernel 3: A16[n][f] = fp16((p-g)^2 - mean) ----------------
__global__ void a16_kernel(const float* __restrict__ probe,
                           const float* __restrict__ gallery) {
    const int i = blockIdx.x;
    const int jc = blockIdx.y;
    const int f0 = threadIdx.x * 8;
    float4 p0 = *(const float4*)&probe[(size_t)i * FEAT + f0];
    float4 p1 = *(const float4*)&probe[(size_t)i * FEAT + f0 + 4];
    float4 m0 = *(const float4*)&g_mean[f0];
    float4 m1 = *(const float4*)&g_mean[f0 + 4];
    #pragma unroll 4
    for (int jj = 0; jj < 16; jj++) {
        const int j = jc * 16 + jj;
        float4 gv0 = *(const float4*)&gallery[(size_t)j * FEAT + f0];
        float4 gv1 = *(const float4*)&gallery[(size_t)j * FEAT + f0 + 4];
        float d[8];
        d[0] = p0.x - gv0.x; d[0] = d[0] * d[0] - m0.x;
        d[1] = p0.y - gv0.y; d[1] = d[1] * d[1] - m0.y;
        d[2] = p0.z - gv0.z; d[2] = d[2] * d[2] - m0.z;
        d[3] = p0.w - gv0.w; d[3] = d[3] * d[3] - m0.w;
        d[4] = p1.x - gv1.x; d[4] = d[4] * d[4] - m1.x;
        d[5] = p1.y - gv1.y; d[5] = d[5] * d[5] - m1.y;
        d[6] = p1.z - gv1.z; d[6] = d[6] * d[6] - m1.z;
        d[7] = p1.w - gv1.w; d[7] = d[7] * d[7] - m1.w;
        __half h[8];
        #pragma unroll
        for (int k = 0; k < 8; k++) h[k] = __float2half_rn(d[k]);
        *(uint4*)&g_A16[(size_t)(i * NGALLERY + j) * FEAT + f0] = *(uint4*)h;
    }
}

// ---------------- kernel 4: fp16 HMMA GEMM, reg-pipelined ----------------
__global__ void __launch_bounds__(THREADS, 1)
gemm_kernel(float* __restrict__ out) {
    extern __shared__ char smem[];
    const uint32_t sb = smem_u32(smem);
    const int tid = threadIdx.x;
    const int lid = tid & 31;
    const int wid = tid >> 5;

    const int ct = blockIdx.x;            // 0..2
    const int rt = blockIdx.y;            // 0..127
    const int n0 = rt * BM;
    const int c0 = ct * BN;

    const int pr = tid >> 3;
    const int pu = tid & 7;

    const int wm = wid >> 2;              // 0..1
    const int wn = wid & 3;               // 0..3
    const int mbase = wm * 64;
    const int nbase = wn * 64;
    const int a_row  = ((lid >> 3) & 1) * 8 + (lid & 7);
    const int a_colb = (lid >> 4) * 16;
    const int b_row  = (lid >> 4) * 8 + (lid & 7);
    const int b_colb = ((lid >> 3) & 1) * 16;

    float acc[4][8][4];
    #pragma unroll
    for (int im = 0; im < 4; im++)
        #pragma unroll
        for (int in = 0; in < 8; in++)
            #pragma unroll
            for (int r = 0; r < 4; r++) acc[im][in][r] = 0.f;

    auto issue = [&](int kt) {
        const uint32_t st = (uint32_t)(kt & (NSTAGES - 1)) * STAGE_BYTES;
        const int k0 = kt * BK;
        #pragma unroll
        for (int c = 0; c < 4; c++) {
            int row = pr + c * 32;
            cp16(sb + st + sw128(row * 128 + pu * 16),
                 &g_A16[(size_t)(n0 + row) * FEAT + k0 + pu * 8]);
        }
        #pragma unroll
        for (int c = 0; c < 8; c++) {
            int row = pr + c * 32;
            cp16(sb + st + 16384 + sw128(row * 128 + pu * 16),
                 &g_W16[(size_t)(c0 + row) * FEAT + k0 + pu * 8]);
        }
    };

    issue(0); CP_COMMIT();
    issue(1); CP_COMMIT();
    issue(2); CP_COMMIT();

    uint32_t afr[2][4][4];
    uint32_t bfr[2][16];

    for (int kt = 0; kt < KITERS; kt++) {
        CP_WAIT2();
        __syncthreads();
        if (kt + 3 < KITERS) issue(kt + 3);
        CP_COMMIT();

        const uint32_t abuf = sb + (uint32_t)(kt & (NSTAGES - 1)) * STAGE_BYTES;
        const uint32_t bbuf = abuf + 16384;

        // preload ik=0 fragments
        #pragma unroll
        for (int im = 0; im < 4; im++)
            ldsm4(afr[0][im], abuf +
                  sw128((mbase + im * 16 + a_row) * 128 + a_colb));
        #pragma unroll
        for (int nb = 0; nb < 4; nb++)
            ldsm4(&bfr[0][nb * 4], bbuf +
                  sw128((nbase + nb * 16 + b_row) * 128 + b_colb));

        #pragma unroll
        for (int ik = 0; ik < 4; ik++) {
            const int cur = ik & 1, nxt = cur ^ 1;
            if (ik < 3) {   // prefetch ik+1 while computing ik
                #pragma unroll
                for (int im = 0; im < 4; im++)
                    ldsm4(afr[nxt][im], abuf +
                          sw128((mbase + im * 16 + a_row) * 128 + (ik + 1) * 32 + a_colb));
                #pragma unroll
                for (int nb = 0; nb < 4; nb++)
                    ldsm4(&bfr[nxt][nb * 4], bbuf +
                          sw128((nbase + nb * 16 + b_row) * 128 + (ik + 1) * 32 + b_colb));
            }
            #pragma unroll
            for (int im = 0; im < 4; im++)
                #pragma unroll
                for (int in = 0; in < 8; in++)
                    mma16816(acc[im][in], afr[cur][im], &bfr[cur][in * 2]);
        }
    }

    // ---- epilogue: restage through smem, coalesced row stores ----
    __syncthreads();        // k-loop smem reads done; reuse pipeline buffers
    float* stage = reinterpret_cast<float*>(smem);   // 128 x 256 fp32 = 128KB
    #pragma unroll
    for (int im = 0; im < 4; im++) {
        #pragma unroll
        for (int in = 0; in < 8; in++) {
            const int r = mbase + im * 16 + (lid >> 2);
            const int c = nbase + in * 8 + (lid & 3) * 2;
            stage[r * 256 + c]             = acc[im][in][0] * WSCALE_INV;
            stage[r * 256 + c + 1]         = acc[im][in][1] * WSCALE_INV;
            stage[(r + 8) * 256 + c]       = acc[im][in][2] * WSCALE_INV;
            stage[(r + 8) * 256 + c + 1]   = acc[im][in][3] * WSCALE_INV;
        }
    }
    __syncthreads();
    const int col = c0 + tid;
    if (col < NCLS) {
        const float cc = g_cconst[col];
        #pragma unroll 8
        for (int r = 0; r < BM; r++)
            out[(size_t)(n0 + r) * NCLS + col] = stage[r * 256 + tid] + cc;
    }
}

// ---------------- launch ----------------
extern "C" void kernel_launch(void* const* d_in, const int* in_sizes, int n_in,
                              void* d_out, int out_size) {
    const float* probe   = (const float*)d_in[0];
    const float* gallery = (const float*)d_in[1];
    const float* gamma   = (const float*)d_in[2];
    const float* beta    = (const float*)d_in[3];
    const float* W       = (const float*)d_in[4];
    const float* bias    = (const float*)d_in[5];
    float* out = (float*)d_out;

    stats_part_kernel<<<dim3(8, 10), 256>>>(probe, gallery);
    stats_final_kernel<<<8, 256>>>(gamma);
    a16_kernel<<<dim3(64, 16), 256>>>(probe, gallery);
    prep_kernel<<<NPAD, 256>>>(W, beta, bias);

    static bool attr_set = false;
    if (!attr_set) {
        cudaFuncSetAttribute(gemm_kernel,
                             cudaFuncAttributeMaxDynamicSharedMemorySize, SMEM_TOTAL);
        attr_set = true;
    }
    gemm_kernel<<<dim3(3, 128, 1), THREADS, SMEM_TOTAL>>>(out);
}

// round 5
// speedup vs baseline: 1.1714x; 1.0328x over previous
#include <cuda_runtime.h>
#include <cuda_fp16.h>
#include <cstdint>

#define FEAT      2048
#define NPROBE    64
#define NGALLERY  256
#define NROWS     16384           // NPROBE * NGALLERY
#define NCLS      751
#define NPAD      768
#define BN_EPS    1e-5f

#define BM        128
#define BN        256
#define BK        64
#define KITERS    (FEAT / BK)     // 32
#define THREADS   512             // 16 warps, warp tile 64x32
#define WSCALE    64.0f
#define WSCALE_INV (1.0f / 64.0f)

// 4-stage smem pipeline: per stage A 16KB + B 32KB = 48KB
#define STAGE_BYTES 49152
#define NSTAGES     4
#define SMEM_TOTAL  (NSTAGES * STAGE_BYTES)   // 192 KB

#define NPART 10

// ---------------- device scratch ----------------
__device__ __align__(16) float g_part[NPART * 4 * FEAT];
__device__ __align__(16) float g_scale[FEAT];
__device__ __align__(16) float g_mean[FEAT];
__device__ __align__(16) float g_cconst[NPAD];
__device__ __align__(16) __half g_W16[NPAD * FEAT];          // 3 MB
__device__ __align__(16) __half g_A16[(size_t)NROWS * FEAT]; // 64 MB

// ---------------- helpers ----------------
__device__ __forceinline__ uint32_t smem_u32(const void* p) {
    uint32_t a;
    asm("{ .reg .u64 t; cvta.to.shared.u64 t, %1; cvt.u32.u64 %0, t; }"
        : "=r"(a) : "l"(p));
    return a;
}
__device__ __forceinline__ uint32_t sw128(uint32_t off) {
    return off ^ ((off >> 3) & 0x70);
}
__device__ __forceinline__ void cp16(uint32_t dst, const void* src) {
    asm volatile("cp.async.cg.shared.global [%0], [%1], 16;"
                 :: "r"(dst), "l"(src) : "memory");
}
#define CP_COMMIT() asm volatile("cp.async.commit_group;" ::: "memory")
#define CP_WAIT2()  asm volatile("cp.async.wait_group 2;" ::: "memory")

__device__ __forceinline__ void ldsm4(uint32_t* r, uint32_t addr) {
    asm volatile("ldmatrix.sync.aligned.m8n8.x4.shared.b16 {%0,%1,%2,%3}, [%4];"
                 : "=r"(r[0]), "=r"(r[1]), "=r"(r[2]), "=r"(r[3]) : "r"(addr));
}
__device__ __forceinline__ void mma16816(float* c, const uint32_t* a,
                                         const uint32_t* b) {
    asm volatile(
        "mma.sync.aligned.m16n8k16.row.col.f32.f16.f16.f32 "
        "{%0,%1,%2,%3}, {%4,%5,%6,%7}, {%8,%9}, {%0,%1,%2,%3};"
        : "+f"(c[0]), "+f"(c[1]), "+f"(c[2]), "+f"(c[3])
        : "r"(a[0]), "r"(a[1]), "r"(a[2]), "r"(a[3]), "r"(b[0]), "r"(b[1]));
}

// ---------------- kernel 1a: partial moments ----------------
__global__ void stats_part_kernel(const float* __restrict__ probe,
                                  const float* __restrict__ gallery) {
    const int f = blockIdx.x * 256 + threadIdx.x;
    const int y = blockIdx.y;
    const float* src = (y < 2) ? probe : gallery;
    const int r0 = (y < 2) ? y * 32 : (y - 2) * 32;
    float s1 = 0.f, s2 = 0.f, s3 = 0.f, s4 = 0.f;
    #pragma unroll 8
    for (int r = 0; r < 32; r++) {
        float v = src[(size_t)(r0 + r) * FEAT + f];
        float v2 = v * v;
        s1 += v; s2 += v2; s3 += v2 * v; s4 += v2 * v2;
    }
    g_part[(y * 4 + 0) * FEAT + f] = s1;
    g_part[(y * 4 + 1) * FEAT + f] = s2;
    g_part[(y * 4 + 2) * FEAT + f] = s3;
    g_part[(y * 4 + 3) * FEAT + f] = s4;
}

// ---------------- kernel 1b: finalize BN stats ----------------
__global__ void stats_final_kernel(const float* __restrict__ gamma) {
    const int f = blockIdx.x * 256 + threadIdx.x;
    float sp1 = 0.f, sp2 = 0.f, sp3 = 0.f, sp4 = 0.f;
    float sg1 = 0.f, sg2 = 0.f, sg3 = 0.f, sg4 = 0.f;
    #pragma unroll
    for (int y = 0; y < 2; y++) {
        sp1 += g_part[(y * 4 + 0) * FEAT + f];
        sp2 += g_part[(y * 4 + 1) * FEAT + f];
        sp3 += g_part[(y * 4 + 2) * FEAT + f];
        sp4 += g_part[(y * 4 + 3) * FEAT + f];
    }
    #pragma unroll
    for (int y = 2; y < 10; y++) {
        sg1 += g_part[(y * 4 + 0) * FEAT + f];
        sg2 += g_part[(y * 4 + 1) * FEAT + f];
        sg3 += g_part[(y * 4 + 2) * FEAT + f];
        sg4 += g_part[(y * 4 + 3) * FEAT + f];
    }
    const float ip = 1.f / NPROBE, ig = 1.f / NGALLERY;
    float mp1 = sp1 * ip, mp2 = sp2 * ip, mp3 = sp3 * ip, mp4 = sp4 * ip;
    float mg1 = sg1 * ig, mg2 = sg2 * ig, mg3 = sg3 * ig, mg4 = sg4 * ig;
    float mean = mp2 + mg2 - 2.f * mp1 * mg1;
    float ed2  = mp4 - 4.f * mp3 * mg1 + 6.f * mp2 * mg2 - 4.f * mp1 * mg3 + mg4;
    float var  = ed2 - mean * mean;
    g_mean[f]  = mean;
    g_scale[f] = gamma[f] * rsqrtf(var + BN_EPS);
}

// ---------------- kernel 2: fused A16 build + W prep ----------------
// blocks [0,1024): A16[i*256+j][f] = fp16((p-g)^2 - mean)
// blocks [1024,1792): W16[c] = fp16(w*scale*WSCALE), cconst[c]
__global__ void fused_prep_kernel(const float* __restrict__ probe,
                                  const float* __restrict__ gallery,
                                  const float* __restrict__ W,
                                  const float* __restrict__ beta,
                                  const float* __restrict__ bias) {
    const int bx = blockIdx.x;
    const int tid = threadIdx.x;
    if (bx < 1024) {
        const int i = bx >> 4;
        const int jc = bx & 15;
        const int f0 = tid * 8;
        float4 p0 = *(const float4*)&probe[(size_t)i * FEAT + f0];
        float4 p1 = *(const float4*)&probe[(size_t)i * FEAT + f0 + 4];
        float4 m0 = *(const float4*)&g_mean[f0];
        float4 m1 = *(const float4*)&g_mean[f0 + 4];
        #pragma unroll 4
        for (int jj = 0; jj < 16; jj++) {
            const int j = jc * 16 + jj;
            float4 gv0 = *(const float4*)&gallery[(size_t)j * FEAT + f0];
            float4 gv1 = *(const float4*)&gallery[(size_t)j * FEAT + f0 + 4];
            float d[8];
            d[0] = p0.x - gv0.x; d[0] = d[0] * d[0] - m0.x;
            d[1] = p0.y - gv0.y; d[1] = d[1] * d[1] - m0.y;
            d[2] = p0.z - gv0.z; d[2] = d[2] * d[2] - m0.z;
            d[3] = p0.w - gv0.w; d[3] = d[3] * d[3] - m0.w;
            d[4] = p1.x - gv1.x; d[4] = d[4] * d[4] - m1.x;
            d[5] = p1.y - gv1.y; d[5] = d[5] * d[5] - m1.y;
            d[6] = p1.z - gv1.z; d[6] = d[6] * d[6] - m1.z;
            d[7] = p1.w - gv1.w; d[7] = d[7] * d[7] - m1.w;
            __half h[8];
            #pragma unroll
            for (int k = 0; k < 8; k++) h[k] = __float2half_rn(d[k]);
            *(uint4*)&g_A16[(size_t)(i * NGALLERY + j) * FEAT + f0] = *(uint4*)h;
        }
    } else {
        const int c = bx - 1024;
        const int f0 = tid * 8;
        float acc = 0.f;
        float w[8];
        if (c < NCLS) {
            float4 w0 = *(const float4*)&W[(size_t)c * FEAT + f0];
            float4 w1 = *(const float4*)&W[(size_t)c * FEAT + f0 + 4];
            w[0] = w0.x; w[1] = w0.y; w[2] = w0.z; w[3] = w0.w;
            w[4] = w1.x; w[5] = w1.y; w[6] = w1.z; w[7] = w1.w;
        } else {
            #pragma unroll
            for (int k = 0; k < 8; k++) w[k] = 0.f;
        }
        __half h[8];
        #pragma unroll
        for (int k = 0; k < 8; k++) {
            float s = g_scale[f0 + k];
            h[k] = __float2half_rn(w[k] * s * WSCALE);
            acc += w[k] * beta[f0 + k];
        }
        *(uint4*)&g_W16[(size_t)c * FEAT + f0] = *(uint4*)h;
        #pragma unroll
        for (int o = 16; o > 0; o >>= 1)
            acc += __shfl_down_sync(0xFFFFFFFFu, acc, o);
        __shared__ float red[8];
        if ((tid & 31) == 0) red[tid >> 5] = acc;
        __syncthreads();
        if (tid == 0) {
            float t = 0.f;
            #pragma unroll
            for (int k = 0; k < 8; k++) t += red[k];
            g_cconst[c] = t + ((c < NCLS) ? bias[c] : 0.f);
        }
    }
}

// ---------------- kernel 3: fp16 HMMA GEMM, 512 threads ----------------
// C[16384,768] = A16 * W16^T. Tile 128x256x64, 16 warps, warp tile 64x32.
__global__ void __launch_bounds__(THREADS, 1)
gemm_kernel(float* __restrict__ out) {
    extern __shared__ char smem[];
    const uint32_t sb = smem_u32(smem);
    const int tid = threadIdx.x;
    const int lid = tid & 31;
    const int wid = tid >> 5;

    const int ct = blockIdx.x;            // 0..2
    const int rt = blockIdx.y;            // 0..127
    const int n0 = rt * BM;
    const int c0 = ct * BN;

    // producer mapping: 16B chunks, 8 per 128B row; 512 threads
    const int pr = tid >> 3;              // row base 0..63
    const int pu = tid & 7;               // chunk in row

    // consumer: warp grid 2 (M) x 8 (N), warp tile 64x32
    const int wm = wid >> 3;              // 0..1
    const int wn = wid & 7;               // 0..7
    const int mbase = wm * 64;
    const int nbase = wn * 32;
    const int a_row  = ((lid >> 3) & 1) * 8 + (lid & 7);
    const int a_colb = (lid >> 4) * 16;
    const int b_row  = (lid >> 4) * 8 + (lid & 7);
    const int b_colb = ((lid >> 3) & 1) * 16;

    float acc[4][4][4];
    #pragma unroll
    for (int im = 0; im < 4; im++)
        #pragma unroll
        for (int in = 0; in < 4; in++)
            #pragma unroll
            for (int r = 0; r < 4; r++) acc[im][in][r] = 0.f;

    auto issue = [&](int kt) {
        const uint32_t st = (uint32_t)(kt & (NSTAGES - 1)) * STAGE_BYTES;
        const int k0 = kt * BK;
        // A tile: 128 rows x 128B, 2 chunks per thread
        #pragma unroll
        for (int c = 0; c < 2; c++) {
            int row = pr + c * 64;
            cp16(sb + st + sw128(row * 128 + pu * 16),
                 &g_A16[(size_t)(n0 + row) * FEAT + k0 + pu * 8]);
        }
        // B tile: 256 rows x 128B, 4 chunks per thread
        #pragma unroll
        for (int c = 0; c < 4; c++) {
            int row = pr + c * 64;
            cp16(sb + st + 16384 + sw128(row * 128 + pu * 16),
                 &g_W16[(size_t)(c0 + row) * FEAT + k0 + pu * 8]);
        }
    };

    issue(0); CP_COMMIT();
    issue(1); CP_COMMIT();
    issue(2); CP_COMMIT();

    for (int kt = 0; kt < KITERS; kt++) {
        CP_WAIT2();
        __syncthreads();
        if (kt + 3 < KITERS) issue(kt + 3);
        CP_COMMIT();

        const uint32_t abuf = sb + (uint32_t)(kt & (NSTAGES - 1)) * STAGE_BYTES;
        const uint32_t bbuf = abuf + 16384;
        #pragma unroll
        for (int ik = 0; ik < 4; ik++) {
            uint32_t a[4][4];
            #pragma unroll
            for (int im = 0; im < 4; im++)
                ldsm4(a[im], abuf +
                      sw128((mbase + im * 16 + a_row) * 128 + ik * 32 + a_colb));
            uint32_t b[8];
            #pragma unroll
            for (int nb = 0; nb < 2; nb++)
                ldsm4(&b[nb * 4], bbuf +
                      sw128((nbase + nb * 16 + b_row) * 128 + ik * 32 + b_colb));
            #pragma unroll
            for (int im = 0; im < 4; im++)
                #pragma unroll
                for (int in = 0; in < 4; in++)
                    mma16816(acc[im][in], a[im], &b[in * 2]);
        }
    }

    // ---- epilogue: restage through smem, coalesced row stores ----
    __syncthreads();
    float* stage = reinterpret_cast<float*>(smem);   // 128 x 256 fp32 = 128KB
    #pragma unroll
    for (int im = 0; im < 4; im++) {
        #pragma unroll
        for (int in = 0; in < 4; in++) {
            const int r = mbase + im * 16 + (lid >> 2);
            const int c = nbase + in * 8 + (lid & 3) * 2;
            stage[r * 256 + c]           = acc[im][in][0] * WSCALE_INV;
            stage[r * 256 + c + 1]       = acc[im][in][1] * WSCALE_INV;
            stage[(r + 8) * 256 + c]     = acc[im][in][2] * WSCALE_INV;
            stage[(r + 8) * 256 + c + 1] = acc[im][in][3] * WSCALE_INV;
        }
    }
    __syncthreads();
    const int col = c0 + (tid & 255);
    const int rhalf = (tid >> 8) * 64;          // 0 or 64
    if (col < NCLS) {
        const float cc = g_cconst[col];
        #pragma unroll 8
        for (int r = 0; r < 64; r++)
            out[(size_t)(n0 + rhalf + r) * NCLS + col] =
                stage[(rhalf + r) * 256 + (tid & 255)] + cc;
    }
}

// ---------------- launch ----------------
extern "C" void kernel_launch(void* const* d_in, const int* in_sizes, int n_in,
                              void* d_out, int out_size) {
    const float* probe   = (const float*)d_in[0];
    const float* gallery = (const float*)d_in[1];
    const float* gamma   = (const float*)d_in[2];
    const float* beta    = (const float*)d_in[3];
    const float* W       = (const float*)d_in[4];
    const float* bias    = (const float*)d_in[5];
    float* out = (float*)d_out;

    stats_part_kernel<<<dim3(8, 10), 256>>>(probe, gallery);
    stats_final_kernel<<<8, 256>>>(gamma);
    fused_prep_kernel<<<1792, 256>>>(probe, gallery, W, beta, bias);

    static bool attr_set = false;
    if (!attr_set) {
        cudaFuncSetAttribute(gemm_kernel,
                             cudaFuncAttributeMaxDynamicSharedMemorySize, SMEM_TOTAL);
        attr_set = true;
    }
    gemm_kernel<<<dim3(3, 128, 1), THREADS, SMEM_TOTAL>>>(out);
}

// round 6
// speedup vs baseline: 1.1878x; 1.0140x over previous
#include <cuda_runtime.h>
#include <cuda_fp16.h>
#include <cstdint>

#define FEAT      2048
#define NPROBE    64
#define NGALLERY  256
#define NROWS     16384           // NPROBE * NGALLERY
#define NCLS      751
#define NPAD      768
#define BN_EPS    1e-5f

#define BM        128
#define BN        256
#define BK        128
#define KITERS    (FEAT / BK)     // 16
#define THREADS   512             // 16 warps, warp tile 64x32
#define WSCALE    64.0f
#define WSCALE_INV (1.0f / 64.0f)

// 2-stage smem pipeline: per stage A 2x16KB + B 2x32KB = 96KB
#define STAGE_BYTES 98304
#define NSTAGES     2
#define SMEM_TOTAL  (NSTAGES * STAGE_BYTES)   // 192 KB

#define NPART 10

// ---------------- device scratch ----------------
__device__ __align__(16) float g_part[NPART * 4 * FEAT];
__device__ __align__(16) float g_scale[FEAT];
__device__ __align__(16) float g_mean[FEAT];
__device__ __align__(16) float g_cconst[NPAD];
__device__ __align__(16) __half g_W16[NPAD * FEAT];          // 3 MB
__device__ __align__(16) __half g_A16[(size_t)NROWS * FEAT]; // 64 MB

// ---------------- helpers ----------------
__device__ __forceinline__ uint32_t smem_u32(const void* p) {
    uint32_t a;
    asm("{ .reg .u64 t; cvta.to.shared.u64 t, %1; cvt.u32.u64 %0, t; }"
        : "=r"(a) : "l"(p));
    return a;
}
__device__ __forceinline__ uint32_t sw128(uint32_t off) {
    return off ^ ((off >> 3) & 0x70);
}
__device__ __forceinline__ void cp16(uint32_t dst, const void* src) {
    asm volatile("cp.async.cg.shared.global [%0], [%1], 16;"
                 :: "r"(dst), "l"(src) : "memory");
}
#define CP_COMMIT() asm volatile("cp.async.commit_group;" ::: "memory")
#define CP_WAIT1()  asm volatile("cp.async.wait_group 1;" ::: "memory")

__device__ __forceinline__ void ldsm4(uint32_t* r, uint32_t addr) {
    asm volatile("ldmatrix.sync.aligned.m8n8.x4.shared.b16 {%0,%1,%2,%3}, [%4];"
                 : "=r"(r[0]), "=r"(r[1]), "=r"(r[2]), "=r"(r[3]) : "r"(addr));
}
__device__ __forceinline__ void mma16816(float* c, const uint32_t* a,
                                         const uint32_t* b) {
    asm volatile(
        "mma.sync.aligned.m16n8k16.row.col.f32.f16.f16.f32 "
        "{%0,%1,%2,%3}, {%4,%5,%6,%7}, {%8,%9}, {%0,%1,%2,%3};"
        : "+f"(c[0]), "+f"(c[1]), "+f"(c[2]), "+f"(c[3])
        : "r"(a[0]), "r"(a[1]), "r"(a[2]), "r"(a[3]), "r"(b[0]), "r"(b[1]));
}

// ---------------- kernel 1a: partial moments ----------------
__global__ void stats_part_kernel(const float* __restrict__ probe,
                                  const float* __restrict__ gallery) {
    const int f = blockIdx.x * 256 + threadIdx.x;
    const int y = blockIdx.y;
    const float* src = (y < 2) ? probe : gallery;
    const int r0 = (y < 2) ? y * 32 : (y - 2) * 32;
    float s1 = 0.f, s2 = 0.f, s3 = 0.f, s4 = 0.f;
    #pragma unroll 8
    for (int r = 0; r < 32; r++) {
        float v = src[(size_t)(r0 + r) * FEAT + f];
        float v2 = v * v;
        s1 += v; s2 += v2; s3 += v2 * v; s4 += v2 * v2;
    }
    g_part[(y * 4 + 0) * FEAT + f] = s1;
    g_part[(y * 4 + 1) * FEAT + f] = s2;
    g_part[(y * 4 + 2) * FEAT + f] = s3;
    g_part[(y * 4 + 3) * FEAT + f] = s4;
}

// ---------------- kernel 1b: finalize BN stats ----------------
__global__ void stats_final_kernel(const float* __restrict__ gamma) {
    const int f = blockIdx.x * 256 + threadIdx.x;
    float sp1 = 0.f, sp2 = 0.f, sp3 = 0.f, sp4 = 0.f;
    float sg1 = 0.f, sg2 = 0.f, sg3 = 0.f, sg4 = 0.f;
    #pragma unroll
    for (int y = 0; y < 2; y++) {
        sp1 += g_part[(y * 4 + 0) * FEAT + f];
        sp2 += g_part[(y * 4 + 1) * FEAT + f];
        sp3 += g_part[(y * 4 + 2) * FEAT + f];
        sp4 += g_part[(y * 4 + 3) * FEAT + f];
    }
    #pragma unroll
    for (int y = 2; y < 10; y++) {
        sg1 += g_part[(y * 4 + 0) * FEAT + f];
        sg2 += g_part[(y * 4 + 1) * FEAT + f];
        sg3 += g_part[(y * 4 + 2) * FEAT + f];
        sg4 += g_part[(y * 4 + 3) * FEAT + f];
    }
    const float ip = 1.f / NPROBE, ig = 1.f / NGALLERY;
    float mp1 = sp1 * ip, mp2 = sp2 * ip, mp3 = sp3 * ip, mp4 = sp4 * ip;
    float mg1 = sg1 * ig, mg2 = sg2 * ig, mg3 = sg3 * ig, mg4 = sg4 * ig;
    float mean = mp2 + mg2 - 2.f * mp1 * mg1;
    float ed2  = mp4 - 4.f * mp3 * mg1 + 6.f * mp2 * mg2 - 4.f * mp1 * mg3 + mg4;
    float var  = ed2 - mean * mean;
    g_mean[f]  = mean;
    g_scale[f] = gamma[f] * rsqrtf(var + BN_EPS);
}

// ---------------- kernel 2: fused A16 build + W prep ----------------
__global__ void fused_prep_kernel(const float* __restrict__ probe,
                                  const float* __restrict__ gallery,
                                  const float* __restrict__ W,
                                  const float* __restrict__ beta,
                                  const float* __restrict__ bias) {
    const int bx = blockIdx.x;
    const int tid = threadIdx.x;
    if (bx < 1024) {
        const int i = bx >> 4;
        const int jc = bx & 15;
        const int f0 = tid * 8;
        float4 p0 = *(const float4*)&probe[(size_t)i * FEAT + f0];
        float4 p1 = *(const float4*)&probe[(size_t)i * FEAT + f0 + 4];
        float4 m0 = *(const float4*)&g_mean[f0];
        float4 m1 = *(const float4*)&g_mean[f0 + 4];
        #pragma unroll 4
        for (int jj = 0; jj < 16; jj++) {
            const int j = jc * 16 + jj;
            float4 gv0 = *(const float4*)&gallery[(size_t)j * FEAT + f0];
            float4 gv1 = *(const float4*)&gallery[(size_t)j * FEAT + f0 + 4];
            float d[8];
            d[0] = p0.x - gv0.x; d[0] = d[0] * d[0] - m0.x;
            d[1] = p0.y - gv0.y; d[1] = d[1] * d[1] - m0.y;
            d[2] = p0.z - gv0.z; d[2] = d[2] * d[2] - m0.z;
            d[3] = p0.w - gv0.w; d[3] = d[3] * d[3] - m0.w;
            d[4] = p1.x - gv1.x; d[4] = d[4] * d[4] - m1.x;
            d[5] = p1.y - gv1.y; d[5] = d[5] * d[5] - m1.y;
            d[6] = p1.z - gv1.z; d[6] = d[6] * d[6] - m1.z;
            d[7] = p1.w - gv1.w; d[7] = d[7] * d[7] - m1.w;
            __half h[8];
            #pragma unroll
            for (int k = 0; k < 8; k++) h[k] = __float2half_rn(d[k]);
            *(uint4*)&g_A16[(size_t)(i * NGALLERY + j) * FEAT + f0] = *(uint4*)h;
        }
    } else {
        const int c = bx - 1024;
        const int f0 = tid * 8;
        float acc = 0.f;
        float w[8];
        if (c < NCLS) {
            float4 w0 = *(const float4*)&W[(size_t)c * FEAT + f0];
            float4 w1 = *(const float4*)&W[(size_t)c * FEAT + f0 + 4];
            w[0] = w0.x; w[1] = w0.y; w[2] = w0.z; w[3] = w0.w;
            w[4] = w1.x; w[5] = w1.y; w[6] = w1.z; w[7] = w1.w;
        } else {
            #pragma unroll
            for (int k = 0; k < 8; k++) w[k] = 0.f;
        }
        __half h[8];
        #pragma unroll
        for (int k = 0; k < 8; k++) {
            float s = g_scale[f0 + k];
            h[k] = __float2half_rn(w[k] * s * WSCALE);
            acc += w[k] * beta[f0 + k];
        }
        *(uint4*)&g_W16[(size_t)c * FEAT + f0] = *(uint4*)h;
        #pragma unroll
        for (int o = 16; o > 0; o >>= 1)
            acc += __shfl_down_sync(0xFFFFFFFFu, acc, o);
        __shared__ float red[8];
        if ((tid & 31) == 0) red[tid >> 5] = acc;
        __syncthreads();
        if (tid == 0) {
            float t = 0.f;
            #pragma unroll
            for (int k = 0; k < 8; k++) t += red[k];
            g_cconst[c] = t + ((c < NCLS) ? bias[c] : 0.f);
        }
    }
}

// ---------------- kernel 3: fp16 HMMA GEMM, BK=128, 2-stage ----------------
// C[16384,768] = A16 * W16^T. Tile 128x256x128, 16 warps, warp tile 64x32.
// Each stage holds two 64-col halves per operand (A: 2x16KB, B: 2x32KB).
__global__ void __launch_bounds__(THREADS, 1)
gemm_kernel(float* __restrict__ out) {
    extern __shared__ char smem[];
    const uint32_t sb = smem_u32(smem);
    const int tid = threadIdx.x;
    const int lid = tid & 31;
    const int wid = tid >> 5;

    const int ct = blockIdx.x;            // 0..2
    const int rt = blockIdx.y;            // 0..127
    const int n0 = rt * BM;
    const int c0 = ct * BN;

    const int pr = tid >> 3;              // row base 0..63
    const int pu = tid & 7;               // 16B chunk in 128B row

    const int wm = wid >> 3;              // 0..1
    const int wn = wid & 7;               // 0..7
    const int mbase = wm * 64;
    const int nbase = wn * 32;
    const int a_row  = ((lid >> 3) & 1) * 8 + (lid & 7);
    const int a_colb = (lid >> 4) * 16;
    const int b_row  = (lid >> 4) * 8 + (lid & 7);
    const int b_colb = ((lid >> 3) & 1) * 16;

    float acc[4][4][4];
    #pragma unroll
    for (int im = 0; im < 4; im++)
        #pragma unroll
        for (int in = 0; in < 4; in++)
            #pragma unroll
            for (int r = 0; r < 4; r++) acc[im][in][r] = 0.f;

    auto issue = [&](int kt) {
        const uint32_t st = (uint32_t)(kt & 1) * STAGE_BYTES;
        const int k0 = kt * BK;
        // A: 2 halves x 128 rows x 128B (2 chunks/thread/half)
        #pragma unroll
        for (int h = 0; h < 2; h++)
            #pragma unroll
            for (int c = 0; c < 2; c++) {
                int row = pr + c * 64;
                cp16(sb + st + h * 16384 + sw128(row * 128 + pu * 16),
                     &g_A16[(size_t)(n0 + row) * FEAT + k0 + h * 64 + pu * 8]);
            }
        // B: 2 halves x 256 rows x 128B (4 chunks/thread/half)
        #pragma unroll
        for (int h = 0; h < 2; h++)
            #pragma unroll
            for (int c = 0; c < 4; c++) {
                int row = pr + c * 64;
                cp16(sb + st + 32768 + h * 32768 + sw128(row * 128 + pu * 16),
                     &g_W16[(size_t)(c0 + row) * FEAT + k0 + h * 64 + pu * 8]);
            }
    };

    issue(0); CP_COMMIT();
    issue(1); CP_COMMIT();

    for (int kt = 0; kt < KITERS; kt++) {
        CP_WAIT1();            // stage kt resident (stage kt+1 may pend)
        __syncthreads();

        const uint32_t st = sb + (uint32_t)(kt & 1) * STAGE_BYTES;
        #pragma unroll
        for (int ik = 0; ik < 8; ik++) {
            const int h = ik >> 2, iku = ik & 3;
            const uint32_t abuf = st + h * 16384;
            const uint32_t bbuf = st + 32768 + h * 32768;
            uint32_t a[4][4];
            #pragma unroll
            for (int im = 0; im < 4; im++)
                ldsm4(a[im], abuf +
                      sw128((mbase + im * 16 + a_row) * 128 + iku * 32 + a_colb));
            uint32_t b[8];
            #pragma unroll
            for (int nb = 0; nb < 2; nb++)
                ldsm4(&b[nb * 4], bbuf +
                      sw128((nbase + nb * 16 + b_row) * 128 + iku * 32 + b_colb));
            #pragma unroll
            for (int im = 0; im < 4; im++)
                #pragma unroll
                for (int in = 0; in < 4; in++)
                    mma16816(acc[im][in], a[im], &b[in * 2]);
        }

        __syncthreads();       // all reads of stage kt done; buffer reusable
        if (kt + 2 < KITERS) issue(kt + 2);
        CP_COMMIT();           // empty group at tail keeps wait-count invariant
    }

    // ---- epilogue: restage through smem, coalesced row stores ----
    float* stage = reinterpret_cast<float*>(smem);   // 128 x 256 fp32 = 128KB
    #pragma unroll
    for (int im = 0; im < 4; im++) {
        #pragma unroll
        for (int in = 0; in < 4; in++) {
            const int r = mbase + im * 16 + (lid >> 2);
            const int c = nbase + in * 8 + (lid & 3) * 2;
            stage[r * 256 + c]           = acc[im][in][0] * WSCALE_INV;
            stage[r * 256 + c + 1]       = acc[im][in][1] * WSCALE_INV;
            stage[(r + 8) * 256 + c]     = acc[im][in][2] * WSCALE_INV;
            stage[(r + 8) * 256 + c + 1] = acc[im][in][3] * WSCALE_INV;
        }
    }
    __syncthreads();
    const int col = c0 + (tid & 255);
    const int rhalf = (tid >> 8) * 64;          // 0 or 64
    if (col < NCLS) {
        const float cc = g_cconst[col];
        #pragma unroll 8
        for (int r = 0; r < 64; r++)
            out[(size_t)(n0 + rhalf + r) * NCLS + col] =
                stage[(rhalf + r) * 256 + (tid & 255)] + cc;
    }
}

// ---------------- launch ----------------
extern "C" void kernel_launch(void* const* d_in, const int* in_sizes, int n_in,
                              void* d_out, int out_size) {
    const float* probe   = (const float*)d_in[0];
    const float* gallery = (const float*)d_in[1];
    const float* gamma   = (const float*)d_in[2];
    const float* beta    = (const float*)d_in[3];
    const float* W       = (const float*)d_in[4];
    const float* bias    = (const float*)d_in[5];
    float* out = (float*)d_out;

    stats_part_kernel<<<dim3(8, 10), 256>>>(probe, gallery);
    stats_final_kernel<<<8, 256>>>(gamma);
    fused_prep_kernel<<<1792, 256>>>(probe, gallery, W, beta, bias);

    static bool attr_set = false;
    if (!attr_set) {
        cudaFuncSetAttribute(gemm_kernel,
                             cudaFuncAttributeMaxDynamicSharedMemorySize, SMEM_TOTAL);
        attr_set = true;
    }
    gemm_kernel<<<dim3(3, 128, 1), THREADS, SMEM_TOTAL>>>(out);
}

// round 7
// speedup vs baseline: 1.2300x; 1.0356x over previous
#include <cuda_runtime.h>
#include <cuda_fp16.h>
#include <cstdint>

#define FEAT      2048
#define NPROBE    64
#define NGALLERY  256
#define NROWS     16384           // NPROBE * NGALLERY
#define NCLS      751
#define NPAD      768
#define BN_EPS    1e-5f

#define BM        128
#define BN        128
#define BK        64
#define KITERS    (FEAT / BK)     // 32
#define THREADS   256             // 8 warps, warp tile 64x32, 2 CTAs/SM
#define WSCALE    64.0f
#define WSCALE_INV (1.0f / 64.0f)

// 3-stage smem pipeline: per stage A 16KB + B 16KB = 32KB
#define STAGE_BYTES 32768
#define NSTAGES     3
#define SMEM_TOTAL  (NSTAGES * STAGE_BYTES)   // 96 KB -> 2 CTAs/SM

#define EPI_STRIDE  132           // fp32 words, bank-conflict-free restage

#define NPART 10

// ---------------- device scratch ----------------
__device__ __align__(16) float g_part[NPART * 4 * FEAT];
__device__ __align__(16) float g_scale[FEAT];
__device__ __align__(16) float g_mean[FEAT];
__device__ __align__(16) float g_cconst[NPAD];
__device__ __align__(16) __half g_W16[NPAD * FEAT];          // 3 MB
__device__ __align__(16) __half g_A16[(size_t)NROWS * FEAT]; // 64 MB

// ---------------- helpers ----------------
__device__ __forceinline__ uint32_t smem_u32(const void* p) {
    uint32_t a;
    asm("{ .reg .u64 t; cvta.to.shared.u64 t, %1; cvt.u32.u64 %0, t; }"
        : "=r"(a) : "l"(p));
    return a;
}
__device__ __forceinline__ uint32_t sw128(uint32_t off) {
    return off ^ ((off >> 3) & 0x70);
}
__device__ __forceinline__ void cp16(uint32_t dst, const void* src) {
    asm volatile("cp.async.cg.shared.global [%0], [%1], 16;"
                 :: "r"(dst), "l"(src) : "memory");
}
#define CP_COMMIT() asm volatile("cp.async.commit_group;" ::: "memory")
#define CP_WAIT2()  asm volatile("cp.async.wait_group 2;" ::: "memory")

__device__ __forceinline__ void ldsm4(uint32_t* r, uint32_t addr) {
    asm volatile("ldmatrix.sync.aligned.m8n8.x4.shared.b16 {%0,%1,%2,%3}, [%4];"
                 : "=r"(r[0]), "=r"(r[1]), "=r"(r[2]), "=r"(r[3]) : "r"(addr));
}
__device__ __forceinline__ void mma16816(float* c, const uint32_t* a,
                                         const uint32_t* b) {
    asm volatile(
        "mma.sync.aligned.m16n8k16.row.col.f32.f16.f16.f32 "
        "{%0,%1,%2,%3}, {%4,%5,%6,%7}, {%8,%9}, {%0,%1,%2,%3};"
        : "+f"(c[0]), "+f"(c[1]), "+f"(c[2]), "+f"(c[3])
        : "r"(a[0]), "r"(a[1]), "r"(a[2]), "r"(a[3]), "r"(b[0]), "r"(b[1]));
}

// ---------------- kernel 1a: partial moments ----------------
__global__ void stats_part_kernel(const float* __restrict__ probe,
                                  const float* __restrict__ gallery) {
    const int f = blockIdx.x * 256 + threadIdx.x;
    const int y = blockIdx.y;
    const float* src = (y < 2) ? probe : gallery;
    const int r0 = (y < 2) ? y * 32 : (y - 2) * 32;
    float s1 = 0.f, s2 = 0.f, s3 = 0.f, s4 = 0.f;
    #pragma unroll 8
    for (int r = 0; r < 32; r++) {
        float v = src[(size_t)(r0 + r) * FEAT + f];
        float v2 = v * v;
        s1 += v; s2 += v2; s3 += v2 * v; s4 += v2 * v2;
    }
    g_part[(y * 4 + 0) * FEAT + f] = s1;
    g_part[(y * 4 + 1) * FEAT + f] = s2;
    g_part[(y * 4 + 2) * FEAT + f] = s3;
    g_part[(y * 4 + 3) * FEAT + f] = s4;
}

// ---------------- kernel 1b: finalize BN stats ----------------
__global__ void stats_final_kernel(const float* __restrict__ gamma) {
    const int f = blockIdx.x * 256 + threadIdx.x;
    float sp1 = 0.f, sp2 = 0.f, sp3 = 0.f, sp4 = 0.f;
    float sg1 = 0.f, sg2 = 0.f, sg3 = 0.f, sg4 = 0.f;
    #pragma unroll
    for (int y = 0; y < 2; y++) {
        sp1 += g_part[(y * 4 + 0) * FEAT + f];
        sp2 += g_part[(y * 4 + 1) * FEAT + f];
        sp3 += g_part[(y * 4 + 2) * FEAT + f];
        sp4 += g_part[(y * 4 + 3) * FEAT + f];
    }
    #pragma unroll
    for (int y = 2; y < 10; y++) {
        sg1 += g_part[(y * 4 + 0) * FEAT + f];
        sg2 += g_part[(y * 4 + 1) * FEAT + f];
        sg3 += g_part[(y * 4 + 2) * FEAT + f];
        sg4 += g_part[(y * 4 + 3) * FEAT + f];
    }
    const float ip = 1.f / NPROBE, ig = 1.f / NGALLERY;
    float mp1 = sp1 * ip, mp2 = sp2 * ip, mp3 = sp3 * ip, mp4 = sp4 * ip;
    float mg1 = sg1 * ig, mg2 = sg2 * ig, mg3 = sg3 * ig, mg4 = sg4 * ig;
    float mean = mp2 + mg2 - 2.f * mp1 * mg1;
    float ed2  = mp4 - 4.f * mp3 * mg1 + 6.f * mp2 * mg2 - 4.f * mp1 * mg3 + mg4;
    float var  = ed2 - mean * mean;
    g_mean[f]  = mean;
    g_scale[f] = gamma[f] * rsqrtf(var + BN_EPS);
}

// ---------------- kernel 2: fused A16 build + W prep ----------------
__global__ void fused_prep_kernel(const float* __restrict__ probe,
                                  const float* __restrict__ gallery,
                                  const float* __restrict__ W,
                                  const float* __restrict__ beta,
                                  const float* __restrict__ bias) {
    const int bx = blockIdx.x;
    const int tid = threadIdx.x;
    if (bx < 1024) {
        const int i = bx >> 4;
        const int jc = bx & 15;
        const int f0 = tid * 8;
        float4 p0 = *(const float4*)&probe[(size_t)i * FEAT + f0];
        float4 p1 = *(const float4*)&probe[(size_t)i * FEAT + f0 + 4];
        float4 m0 = *(const float4*)&g_mean[f0];
        float4 m1 = *(const float4*)&g_mean[f0 + 4];
        #pragma unroll 4
        for (int jj = 0; jj < 16; jj++) {
            const int j = jc * 16 + jj;
            float4 gv0 = *(const float4*)&gallery[(size_t)j * FEAT + f0];
            float4 gv1 = *(const float4*)&gallery[(size_t)j * FEAT + f0 + 4];
            float d[8];
            d[0] = p0.x - gv0.x; d[0] = d[0] * d[0] - m0.x;
            d[1] = p0.y - gv0.y; d[1] = d[1] * d[1] - m0.y;
            d[2] = p0.z - gv0.z; d[2] = d[2] * d[2] - m0.z;
            d[3] = p0.w - gv0.w; d[3] = d[3] * d[3] - m0.w;
            d[4] = p1.x - gv1.x; d[4] = d[4] * d[4] - m1.x;
            d[5] = p1.y - gv1.y; d[5] = d[5] * d[5] - m1.y;
            d[6] = p1.z - gv1.z; d[6] = d[6] * d[6] - m1.z;
            d[7] = p1.w - gv1.w; d[7] = d[7] * d[7] - m1.w;
            __half h[8];
            #pragma unroll
            for (int k = 0; k < 8; k++) h[k] = __float2half_rn(d[k]);
            *(uint4*)&g_A16[(size_t)(i * NGALLERY + j) * FEAT + f0] = *(uint4*)h;
        }
    } else {
        const int c = bx - 1024;
        const int f0 = tid * 8;
        float acc = 0.f;
        float w[8];
        if (c < NCLS) {
            float4 w0 = *(const float4*)&W[(size_t)c * FEAT + f0];
            float4 w1 = *(const float4*)&W[(size_t)c * FEAT + f0 + 4];
            w[0] = w0.x; w[1] = w0.y; w[2] = w0.z; w[3] = w0.w;
            w[4] = w1.x; w[5] = w1.y; w[6] = w1.z; w[7] = w1.w;
        } else {
            #pragma unroll
            for (int k = 0; k < 8; k++) w[k] = 0.f;
        }
        __half h[8];
        #pragma unroll
        for (int k = 0; k < 8; k++) {
            float s = g_scale[f0 + k];
            h[k] = __float2half_rn(w[k] * s * WSCALE);
            acc += w[k] * beta[f0 + k];
        }
        *(uint4*)&g_W16[(size_t)c * FEAT + f0] = *(uint4*)h;
        #pragma unroll
        for (int o = 16; o > 0; o >>= 1)
            acc += __shfl_down_sync(0xFFFFFFFFu, acc, o);
        __shared__ float red[8];
        if ((tid & 31) == 0) red[tid >> 5] = acc;
        __syncthreads();
        if (tid == 0) {
            float t = 0.f;
            #pragma unroll
            for (int k = 0; k < 8; k++) t += red[k];
            g_cconst[c] = t + ((c < NCLS) ? bias[c] : 0.f);
        }
    }
}

// ---------------- kernel 3: fp16 HMMA GEMM, 2 CTAs/SM ----------------
// C[16384,768] = A16 * W16^T. CTA tile 128x128x64, 8 warps (2Mx4N, 64x32),
// 3-stage cp.async pipeline, 2 resident CTAs per SM.
__global__ void __launch_bounds__(THREADS, 2)
gemm_kernel(float* __restrict__ out) {
    extern __shared__ char smem[];
    const uint32_t sb = smem_u32(smem);
    const int tid = threadIdx.x;
    const int lid = tid & 31;
    const int wid = tid >> 5;

    const int ct = blockIdx.x;            // 0..5
    const int rt = blockIdx.y;            // 0..127
    const int n0 = rt * BM;
    const int c0 = ct * BN;

    // producer mapping: 16B chunks, 8 per 128B row; 4 passes over 128 rows
    const int pr = tid >> 3;              // row base 0..31
    const int pu = tid & 7;

    // consumer: warp grid 2 (M) x 4 (N), warp tile 64x32
    const int wm = wid >> 2;              // 0..1
    const int wn = wid & 3;               // 0..3
    const int mbase = wm * 64;
    const int nbase = wn * 32;
    const int a_row  = ((lid >> 3) & 1) * 8 + (lid & 7);
    const int a_colb = (lid >> 4) * 16;
    const int b_row  = (lid >> 4) * 8 + (lid & 7);
    const int b_colb = ((lid >> 3) & 1) * 16;

    float acc[4][4][4];
    #pragma unroll
    for (int im = 0; im < 4; im++)
        #pragma unroll
        for (int in = 0; in < 4; in++)
            #pragma unroll
            for (int r = 0; r < 4; r++) acc[im][in][r] = 0.f;

    auto issue = [&](int kt) {
        const uint32_t st = (uint32_t)((kt % NSTAGES)) * STAGE_BYTES;
        const int k0 = kt * BK;
        #pragma unroll
        for (int c = 0; c < 4; c++) {
            int row = pr + c * 32;
            cp16(sb + st + sw128(row * 128 + pu * 16),
                 &g_A16[(size_t)(n0 + row) * FEAT + k0 + pu * 8]);
            cp16(sb + st + 16384 + sw128(row * 128 + pu * 16),
                 &g_W16[(size_t)(c0 + row) * FEAT + k0 + pu * 8]);
        }
    };

    issue(0); CP_COMMIT();
    issue(1); CP_COMMIT();
    issue(2); CP_COMMIT();

    for (int kt = 0; kt < KITERS; kt++) {
        CP_WAIT2();            // stage kt resident (2 newer may pend)
        __syncthreads();

        const uint32_t abuf = sb + (uint32_t)(kt % NSTAGES) * STAGE_BYTES;
        const uint32_t bbuf = abuf + 16384;
        #pragma unroll
        for (int ik = 0; ik < 4; ik++) {
            uint32_t a[4][4];
            #pragma unroll
            for (int im = 0; im < 4; im++)
                ldsm4(a[im], abuf +
                      sw128((mbase + im * 16 + a_row) * 128 + ik * 32 + a_colb));
            uint32_t b[8];
            #pragma unroll
            for (int nb = 0; nb < 2; nb++)
                ldsm4(&b[nb * 4], bbuf +
                      sw128((nbase + nb * 16 + b_row) * 128 + ik * 32 + b_colb));
            #pragma unroll
            for (int im = 0; im < 4; im++)
                #pragma unroll
                for (int in = 0; in < 4; in++)
                    mma16816(acc[im][in], a[im], &b[in * 2]);
        }

        __syncthreads();       // reads of stage kt done; buffer reusable
        if (kt + 3 < KITERS) { issue(kt + 3); }
        CP_COMMIT();           // keep group-count invariant near the tail
    }

    // ---- epilogue: restage through smem (conflict-free), coalesced stores --
    float* stage = reinterpret_cast<float*>(smem);   // 128 x EPI_STRIDE fp32
    #pragma unroll
    for (int im = 0; im < 4; im++) {
        #pragma unroll
        for (int in = 0; in < 4; in++) {
            const int r = mbase + im * 16 + (lid >> 2);
            const int c = nbase + in * 8 + (lid & 3) * 2;
            stage[r * EPI_STRIDE + c]           = acc[im][in][0] * WSCALE_INV;
            stage[r * EPI_STRIDE + c + 1]       = acc[im][in][1] * WSCALE_INV;
            stage[(r + 8) * EPI_STRIDE + c]     = acc[im][in][2] * WSCALE_INV;
            stage[(r + 8) * EPI_STRIDE + c + 1] = acc[im][in][3] * WSCALE_INV;
        }
    }
    __syncthreads();
    const int col = c0 + (tid & 127);
    const int rhalf = (tid >> 7) * 64;          // 0 or 64
    if (col < NCLS) {
        const float cc = g_cconst[col];
        #pragma unroll 8
        for (int r = 0; r < 64; r++)
            out[(size_t)(n0 + rhalf + r) * NCLS + col] =
                stage[(rhalf + r) * EPI_STRIDE + (tid & 127)] + cc;
    }
}

// ---------------- launch ----------------
extern "C" void kernel_launch(void* const* d_in, const int* in_sizes, int n_in,
                              void* d_out, int out_size) {
    const float* probe   = (const float*)d_in[0];
    const float* gallery = (const float*)d_in[1];
    const float* gamma   = (const float*)d_in[2];
    const float* beta    = (const float*)d_in[3];
    const float* W       = (const float*)d_in[4];
    const float* bias    = (const float*)d_in[5];
    float* out = (float*)d_out;

    stats_part_kernel<<<dim3(8, 10), 256>>>(probe, gallery);
    stats_final_kernel<<<8, 256>>>(gamma);
    fused_prep_kernel<<<1792, 256>>>(probe, gallery, W, beta, bias);

    static bool attr_set = false;
    if (!attr_set) {
        cudaFuncSetAttribute(gemm_kernel,
                             cudaFuncAttributeMaxDynamicSharedMemorySize, SMEM_TOTAL);
        attr_set = true;
    }
    gemm_kernel<<<dim3(6, 128, 1), THREADS, SMEM_TOTAL>>>(out);
}